// round 13
// baseline (speedup 1.0000x reference)
#include <cuda_runtime.h>
#include <math.h>
#include <stdint.h>

// ---------------------------------------------------------------- constants
constexpr int  Bc  = 4;
constexpr int  Sc  = 2048;
constexpr int  Dc  = 512;
constexpr int  Hc  = 8;
constexpr int  DKc = 64;

constexpr long QKV_N   = (long)Bc * Sc * Dc;
constexpr long SCORE_N = (long)Bc * Hc * Sc * Sc;

__device__ float2 g_WT_hl[3 * Dc * Dc];     // Wqkv^T [1536][512] hi/lo
__device__ float2 g_WoT_hl[Dc * Dc];        // Wout^T [512][512] hi/lo
__device__ float  g_Qr[QKV_N];              // raw fp32
__device__ float  g_Kr[QKV_N];
__device__ float  g_V[QKV_N];
__device__ float  g_Vt[QKV_N];              // per (b,h): [dk=64][s=2048] raw
__device__ float  g_ctx[QKV_N];             // raw fp32
__device__ float  g_scores[SCORE_N];        // in-place -> probabilities

// ---------------------------------------------------------------- helpers
__device__ __forceinline__ float to_tf32(float x) {
    float y;
    asm("cvt.rna.tf32.f32 %0, %1;" : "=f"(y) : "f"(x));
    return y;
}
__device__ __forceinline__ uint32_t smem_u32(const void* p) {
    uint32_t a;
    asm("{ .reg .u64 t; cvta.to.shared.u64 t, %1; cvt.u32.u64 %0, t; }"
        : "=r"(a) : "l"(p));
    return a;
}

#define CP_ASYNC16(dst, src) \
    asm volatile("cp.async.cg.shared.global [%0], [%1], 16;" \
                 :: "r"(dst), "l"(src) : "memory")
#define CP_COMMIT() asm volatile("cp.async.commit_group;" ::: "memory")
#define CP_WAIT(n)  asm volatile("cp.async.wait_group %0;" :: "n"(n) : "memory")

#define MMA_TF32(d, A0, A1, A2, A3, B0, B1)                                  \
    asm volatile(                                                            \
        "mma.sync.aligned.m16n8k8.row.col.f32.tf32.tf32.f32 "                \
        "{%0,%1,%2,%3}, {%4,%5,%6,%7}, {%8,%9}, {%0,%1,%2,%3};"              \
        : "+f"((d)[0]), "+f"((d)[1]), "+f"((d)[2]), "+f"((d)[3])             \
        : "r"(__float_as_uint(A0)), "r"(__float_as_uint(A1)),                \
          "r"(__float_as_uint(A2)), "r"(__float_as_uint(A3)),                \
          "r"(__float_as_uint(B0)), "r"(__float_as_uint(B1)))

// ---------------------------------------------------------------- GEMM
// C = alpha * A(MxK) * B^T.  A ALWAYS raw fp32 (in-register tf32 split).
// BHL=1: B pre-split hl float2 [n][k].  BHL=0: B raw fp32.
// NMMA: 1 = ah*bh; 2 = + ah*bl (no A-lo needed); 3 = + al*bh.
// BK=16, 8 warps (MW x NW). Multistage cp.async, ONE barrier per iter.
template<int BM, int BN, int MW, int NW, bool BHL, int NMMA, int PIPE>
__global__ __launch_bounds__(256) void mma_gemm(
    const float* __restrict__ Ap,  int lda, long sAb, long sAh,
    const void* __restrict__ Bp,   int ldb, long sBb, long sBh,
    float* __restrict__ Cp,        int ldc, long sCb, long sCh,
    int K, float alpha)
{
    constexpr int BK = 16;
    constexpr int WM = BM / MW, WN = BN / NW;
    constexpr int MT = WM / 16, NT = WN / 8;
    constexpr int RSA = 20;                      // raw: 16 floats + pad
    constexpr int RSB = BHL ? 40 : 20;
    constexpr int ABYT = BM * RSA * 4;
    constexpr int BBYT = BN * RSB * 4;
    constexpr int STAGE = ABYT + BBYT;
    constexpr int NAC = BM / 64;                 // 16B chunks/thread (A raw)
    constexpr int NBC = BHL ? (BN / 32) : (BN / 64);

    extern __shared__ float sm[];
    const uint32_t sbase = smem_u32(sm);

    const int tid  = threadIdx.x;
    const int wid  = tid >> 5;
    const int lane = tid & 31;
    const int z = blockIdx.z, zb = z / Hc, zh = z % Hc;

    const float*  Ar = Ap + zb * sAb + zh * sAh;
    const float*  Br = (const float*)Bp  + (BHL ? 0 : (zb * sBb + zh * sBh));
    const float2* Bh = (const float2*)Bp + (BHL ? (zb * sBb + zh * sBh) : 0);

    const int m0 = blockIdx.y * BM;
    const int n0 = blockIdx.x * BN;
    const int wm = (wid / NW) * WM;
    const int wn = (wid % NW) * WN;

    float acc[MT][NT][4] = {};

    auto issue = [&](int tile, int buf) {
        const int k0 = tile * BK;
        const uint32_t uA = sbase + buf * STAGE;
        const uint32_t uB = uA + ABYT;
#pragma unroll
        for (int v = 0; v < NAC; v++) {
            int t = tid + v * 256;
            int row = t >> 2, cv = t & 3;
            CP_ASYNC16(uA + row * (RSA * 4) + cv * 16,
                       Ar + (long)(m0 + row) * lda + k0 + cv * 4);
        }
        if constexpr (BHL) {
#pragma unroll
            for (int v = 0; v < NBC; v++) {
                int t = tid + v * 256;
                int row = t >> 3, cv = t & 7;
                CP_ASYNC16(uB + row * (RSB * 4) + cv * 16,
                           Bh + (long)(n0 + row) * ldb + k0 + cv * 2);
            }
        } else {
#pragma unroll
            for (int v = 0; v < NBC; v++) {
                int t = tid + v * 256;
                int row = t >> 2, cv = t & 3;
                CP_ASYNC16(uB + row * (RSB * 4) + cv * 16,
                           Br + (long)(n0 + row) * ldb + k0 + cv * 4);
            }
        }
    };

    auto compute = [&](int buf) {
        const float* sA = sm + (buf * STAGE) / 4;
        const float* sB = sA + ABYT / 4;
        const int mlo = wm + (lane >> 2);
        const int nlo = wn + (lane >> 2);
#pragma unroll
        for (int ks = 0; ks < 2; ks++) {
            const int kb = ks * 8 + (lane & 3);
            float b0h[NT], b0l[NT], b1h[NT], b1l[NT];
#pragma unroll
            for (int nt = 0; nt < NT; nt++) {
                if constexpr (BHL) {
                    const float* bp = sB + (nlo + nt * 8) * RSB + kb * 2;
                    float2 p0 = *(const float2*)(bp);
                    float2 p1 = *(const float2*)(bp + 8);
                    b0h[nt] = p0.x; b0l[nt] = p0.y;
                    b1h[nt] = p1.x; b1l[nt] = p1.y;
                } else {
                    const float* bp = sB + (nlo + nt * 8) * RSB + kb;
                    float x0 = bp[0], x1 = bp[4];
                    b0h[nt] = to_tf32(x0);
                    b1h[nt] = to_tf32(x1);
                    if constexpr (NMMA >= 2) {
                        b0l[nt] = to_tf32(x0 - b0h[nt]);
                        b1l[nt] = to_tf32(x1 - b1h[nt]);
                    }
                }
            }
#pragma unroll
            for (int mt = 0; mt < MT; mt++) {
                const float* ap = sA + (mlo + mt * 16) * RSA + kb;
                float x0 = ap[0], x2 = ap[4];
                float x1 = ap[8 * RSA], x3 = ap[8 * RSA + 4];
                float a0h = to_tf32(x0);
                float a1h = to_tf32(x1);
                float a2h = to_tf32(x2);
                float a3h = to_tf32(x3);
                float a0l, a1l, a2l, a3l;
                if constexpr (NMMA == 3) {
                    a0l = to_tf32(x0 - a0h);
                    a1l = to_tf32(x1 - a1h);
                    a2l = to_tf32(x2 - a2h);
                    a3l = to_tf32(x3 - a3h);
                }
#pragma unroll
                for (int nt = 0; nt < NT; nt++) {
                    MMA_TF32(acc[mt][nt], a0h, a1h, a2h, a3h, b0h[nt], b1h[nt]);
                    if constexpr (NMMA >= 2)
                        MMA_TF32(acc[mt][nt], a0h, a1h, a2h, a3h, b0l[nt], b1l[nt]);
                    if constexpr (NMMA == 3)
                        MMA_TF32(acc[mt][nt], a0l, a1l, a2l, a3l, b0h[nt], b1h[nt]);
                }
            }
        }
    };

    // ---- multistage mainloop: ONE barrier per iteration ----------------
    const int ntile = K / BK;
#pragma unroll
    for (int s = 0; s < PIPE - 1; s++) {
        issue(s, s);
        CP_COMMIT();
    }
    for (int i = 0; i < ntile; i++) {
        CP_WAIT(PIPE - 2);
        __syncthreads();
        compute(i % PIPE);
        const int nx = i + PIPE - 1;
        if (nx < ntile) issue(nx, nx % PIPE);
        CP_COMMIT();
    }

    // ---- epilogue: raw fp32 stores -------------------------------------
    float* C = Cp + zb * sCb + zh * sCh;
#pragma unroll
    for (int mt = 0; mt < MT; mt++) {
        const int row = m0 + wm + mt * 16 + (lane >> 2);
#pragma unroll
        for (int nt = 0; nt < NT; nt++) {
            const int col = n0 + wn + nt * 8 + (lane & 3) * 2;
            float2 o;
            o.x = alpha * acc[mt][nt][0];
            o.y = alpha * acc[mt][nt][1];
            *(float2*)(C + (long)row * ldc + col) = o;
            o.x = alpha * acc[mt][nt][2];
            o.y = alpha * acc[mt][nt][3];
            *(float2*)(C + (long)(row + 8) * ldc + col) = o;
        }
    }
}

// ---------------------------------------------------------------- transpose (raw)
__global__ __launch_bounds__(256) void transpose_kernel(
    const float* __restrict__ in, long sInb, long sInh, int ldin,
    float* __restrict__ out, long sOut, int ldout)
{
    __shared__ float t[32][33];
    const int z = blockIdx.z, zb = z / Hc, zh = z % Hc;
    in  += zb * sInb + zh * sInh;
    out += (long)z * sOut;
    const int c0 = blockIdx.x * 32, r0 = blockIdx.y * 32;
    const int tx = threadIdx.x & 31, ty = threadIdx.x >> 5;
#pragma unroll
    for (int j = 0; j < 32; j += 8)
        t[ty + j][tx] = in[(long)(r0 + ty + j) * ldin + c0 + tx];
    __syncthreads();
#pragma unroll
    for (int j = 0; j < 32; j += 8)
        out[(long)(c0 + ty + j) * ldout + r0 + tx] = t[tx][ty + j];
}

// ---------------------------------------------------------------- transpose + split (weights)
__global__ __launch_bounds__(256) void transpose_split_kernel(
    const float* __restrict__ in, int ldin,
    float2* __restrict__ out, int ldout)
{
    __shared__ float t[32][33];
    const int c0 = blockIdx.x * 32, r0 = blockIdx.y * 32;
    const int tx = threadIdx.x & 31, ty = threadIdx.x >> 5;
#pragma unroll
    for (int j = 0; j < 32; j += 8)
        t[ty + j][tx] = in[(long)(r0 + ty + j) * ldin + c0 + tx];
    __syncthreads();
#pragma unroll
    for (int j = 0; j < 32; j += 8) {
        float v = t[tx][ty + j];
        float hi = to_tf32(v);
        out[(long)(c0 + ty + j) * ldout + r0 + tx] = make_float2(hi, to_tf32(v - hi));
    }
}

// ---------------------------------------------------------------- softmax v4
// Block = (b,q). Mask row staged ONCE into smem (fixes R9's 8x re-read).
// Warp w owns head w's full 2048-col row in registers (MLP=16), shuffle-only
// reductions (fixes R6's 32 barriers), chunked smem mean (no atomics, R7 fix).
__global__ __launch_bounds__(256) void softmax_mean_v4(
    const float* __restrict__ mask, float* __restrict__ attn_out)
{
    __shared__ float smask[Sc];
    __shared__ float sc[Hc][516];

    const int bq   = blockIdx.x;
    const int b    = bq >> 11;
    const int q    = bq & 2047;
    const int tid  = threadIdx.x;
    const int lane = tid & 31;
    const int h    = tid >> 5;          // warp = head

    // stage mask row once (coalesced across the whole block)
    {
        const float4* mrow = (const float4*)(mask + (long)q * Sc);
#pragma unroll
        for (int i = tid; i < Sc / 4; i += 256)
            ((float4*)smask)[i] = mrow[i];
    }
    __syncthreads();

    float4* prow = (float4*)(g_scores + ((long)(b * Hc + h) * Sc + q) * Sc);

    float v[64];
    float mx = -INFINITY;
#pragma unroll
    for (int t = 0; t < 16; t++) {
        float4 x  = prow[lane + t * 32];
        float4 mk = ((const float4*)smask)[lane + t * 32];
        v[t * 4 + 0] = x.x + mk.x;
        v[t * 4 + 1] = x.y + mk.y;
        v[t * 4 + 2] = x.z + mk.z;
        v[t * 4 + 3] = x.w + mk.w;
        mx = fmaxf(mx, fmaxf(fmaxf(v[t * 4], v[t * 4 + 1]),
                             fmaxf(v[t * 4 + 2], v[t * 4 + 3])));
    }
#pragma unroll
    for (int o = 16; o > 0; o >>= 1)
        mx = fmaxf(mx, __shfl_xor_sync(0xffffffffu, mx, o));

    float s = 0.0f;
#pragma unroll
    for (int t = 0; t < 64; t++) {
        v[t] = __expf(v[t] - mx);
        s += v[t];
    }
#pragma unroll
    for (int o = 16; o > 0; o >>= 1)
        s += __shfl_xor_sync(0xffffffffu, s, o);
    const float inv = 1.0f / s;

    float* arow = attn_out + (long)bq * Sc;
#pragma unroll
    for (int chunk = 0; chunk < 4; chunk++) {
#pragma unroll
        for (int t = 0; t < 4; t++) {
            const int tt = chunk * 4 + t;
            float4 o;
            o.x = v[tt * 4 + 0] * inv;
            o.y = v[tt * 4 + 1] * inv;
            o.z = v[tt * 4 + 2] * inv;
            o.w = v[tt * 4 + 3] * inv;
            prow[lane + tt * 32] = o;                       // P write (coalesced)
            *(float4*)&sc[h][(lane + t * 32) * 4] = o;      // stage for mean
        }
        __syncthreads();
#pragma unroll
        for (int j = 0; j < 2; j++) {
            const int lc = tid * 2 + j;
            float acc = sc[0][lc];
#pragma unroll
            for (int hh = 1; hh < Hc; hh++) acc += sc[hh][lc];
            arow[chunk * 512 + lc] = acc * 0.125f;
        }
        __syncthreads();
    }
}

// ---------------------------------------------------------------- launcher
extern "C" void kernel_launch(void* const* d_in, const int* in_sizes, int n_in,
                              void* d_out, int out_size)
{
    (void)in_sizes; (void)n_in; (void)out_size;

    const float* Zq   = (const float*)d_in[0];
    const float* Zkv  = (const float*)d_in[1];
    const float* mask = (const float*)d_in[2];
    const float* Wqkv = (const float*)d_in[3];
    const float* Wout = (const float*)d_in[4];

    float* out      = (float*)d_out;
    float* attn_out = out + QKV_N;

    float2 *gWT, *gWoT;
    float  *gQr, *gKr, *gV, *gVt, *gCtx, *gS;
    cudaGetSymbolAddress((void**)&gWT,  g_WT_hl);
    cudaGetSymbolAddress((void**)&gWoT, g_WoT_hl);
    cudaGetSymbolAddress((void**)&gQr,  g_Qr);
    cudaGetSymbolAddress((void**)&gKr,  g_Kr);
    cudaGetSymbolAddress((void**)&gV,   g_V);
    cudaGetSymbolAddress((void**)&gVt,  g_Vt);
    cudaGetSymbolAddress((void**)&gCtx, g_ctx);
    cudaGetSymbolAddress((void**)&gS,   g_scores);

    // smem per instantiation: PIPE * (BM*RSA + BN*RSB) * 4
    constexpr int SM_PROJ = 4 * (64 * 20 + 128 * 40) * 4;    // 102400 (PIPE=4)
    constexpr int SM_SCR  = 3 * (128 * 20 + 128 * 20) * 4;   // 61440
    constexpr int SM_PV   = 3 * (256 * 20 + 64 * 20) * 4;    // 76800
    cudaFuncSetAttribute(mma_gemm<64, 128, 2, 4, true, 3, 4>,
                         cudaFuncAttributeMaxDynamicSharedMemorySize, SM_PROJ);
    cudaFuncSetAttribute(mma_gemm<64, 128, 2, 4, true, 2, 4>,
                         cudaFuncAttributeMaxDynamicSharedMemorySize, SM_PROJ);
    cudaFuncSetAttribute(mma_gemm<128, 128, 2, 4, false, 3, 3>,
                         cudaFuncAttributeMaxDynamicSharedMemorySize, SM_SCR);
    cudaFuncSetAttribute(mma_gemm<256, 64, 8, 1, false, 1, 3>,
                         cudaFuncAttributeMaxDynamicSharedMemorySize, SM_PV);

    dim3 blk(256);

    // 0) weight prep only (inputs consumed raw)
    transpose_split_kernel<<<dim3(1536 / 32, 512 / 32, 1), blk>>>(
        Wqkv, 3 * Dc, gWT, Dc);
    transpose_split_kernel<<<dim3(512 / 32, 512 / 32, 1), blk>>>(
        Wout, Dc, gWoT, Dc);

    // 1-3) projections: raw Z @ W^T hl, K=512
    //      Q, K: x3 (logit precision).  V: x2 (consumed tf32-truncated).
    {
        dim3 g(Dc / 128, (Bc * Sc) / 64, 1);
        mma_gemm<64, 128, 2, 4, true, 3, 4><<<g, blk, SM_PROJ>>>(
            Zq,  Dc, 0, 0,  gWT,               Dc, 0, 0,  gQr, Dc, 0, 0,  Dc, 1.0f);
        mma_gemm<64, 128, 2, 4, true, 3, 4><<<g, blk, SM_PROJ>>>(
            Zkv, Dc, 0, 0,  gWT + Dc * Dc,     Dc, 0, 0,  gKr, Dc, 0, 0,  Dc, 1.0f);
        mma_gemm<64, 128, 2, 4, true, 2, 4><<<g, blk, SM_PROJ>>>(
            Zkv, Dc, 0, 0,  gWT + 2 * Dc * Dc, Dc, 0, 0,  gV,  Dc, 0, 0,  Dc, 1.0f);
    }

    // 3b) V transpose per (b,h): [s,dk] -> [dk,s] raw
    transpose_kernel<<<dim3(DKc / 32, Sc / 32, Bc * Hc), blk>>>(
        gV, (long)Sc * Dc, DKc, Dc, gVt, (long)DKc * Sc, Sc);

    // 4) scores = 0.125 * Q @ K^T per (b,h): raw operands, in-reg x3
    {
        dim3 g(Sc / 128, Sc / 128, Bc * Hc);
        mma_gemm<128, 128, 2, 4, false, 3, 3><<<g, blk, SM_SCR>>>(
            gQr, Dc, (long)Sc * Dc, DKc,
            gKr, Dc, (long)Sc * Dc, DKc,
            gS, Sc, (long)Hc * Sc * Sc, (long)Sc * Sc,
            DKc, 0.125f);
    }

    // 5) softmax (+mask) in-place + head-mean (v4: mask in smem, warp/head)
    softmax_mean_v4<<<Bc * Sc, blk>>>(mask, attn_out);

    // 6) ctx = P @ V per (b,h): raw P x raw Vt, x1 (hi*hi)
    {
        dim3 g(1, Sc / 256, Bc * Hc);
        mma_gemm<256, 64, 8, 1, false, 1, 3><<<g, blk, SM_PV>>>(
            gS,  Sc, (long)Hc * Sc * Sc, (long)Sc * Sc,
            gVt, Sc, (long)Hc * DKc * Sc, (long)DKc * Sc,
            gCtx, Dc, (long)Sc * Dc, DKc,
            Sc, 1.0f);
    }

    // 7) out = ctx @ Wout: raw ctx @ WoT hl, K=512, x2
    {
        dim3 g(Dc / 128, (Bc * Sc) / 64, 1);
        mma_gemm<64, 128, 2, 4, true, 2, 4><<<g, blk, SM_PROJ>>>(
            gCtx, Dc, 0, 0,  gWoT, Dc, 0, 0,  out, Dc, 0, 0,  Dc, 1.0f);
    }
}

// round 14
// speedup vs baseline: 1.0161x; 1.0161x over previous
#include <cuda_runtime.h>
#include <math.h>
#include <stdint.h>

// ---------------------------------------------------------------- constants
constexpr int  Bc  = 4;
constexpr int  Sc  = 2048;
constexpr int  Dc  = 512;
constexpr int  Hc  = 8;
constexpr int  DKc = 64;

constexpr long QKV_N   = (long)Bc * Sc * Dc;
constexpr long SCORE_N = (long)Bc * Hc * Sc * Sc;

__device__ float2 g_WT_hl[3 * Dc * Dc];     // Wqkv^T [1536][512] hi/lo
__device__ float2 g_WoT_hl[Dc * Dc];        // Wout^T [512][512] hi/lo
__device__ float  g_Qr[QKV_N];              // raw fp32
__device__ float  g_Kr[QKV_N];
__device__ float  g_V[QKV_N];
__device__ float  g_Vt[QKV_N];              // per (b,h): [dk=64][s=2048] raw
__device__ float  g_ctx[QKV_N];             // raw fp32
__device__ float  g_scores[SCORE_N];        // in-place -> probabilities

// ---------------------------------------------------------------- helpers
__device__ __forceinline__ float to_tf32(float x) {
    float y;
    asm("cvt.rna.tf32.f32 %0, %1;" : "=f"(y) : "f"(x));
    return y;
}
__device__ __forceinline__ uint32_t smem_u32(const void* p) {
    uint32_t a;
    asm("{ .reg .u64 t; cvta.to.shared.u64 t, %1; cvt.u32.u64 %0, t; }"
        : "=r"(a) : "l"(p));
    return a;
}

#define CP_ASYNC16(dst, src) \
    asm volatile("cp.async.cg.shared.global [%0], [%1], 16;" \
                 :: "r"(dst), "l"(src) : "memory")
#define CP_COMMIT() asm volatile("cp.async.commit_group;" ::: "memory")
#define CP_WAIT(n)  asm volatile("cp.async.wait_group %0;" :: "n"(n) : "memory")

#define MMA_TF32(d, A0, A1, A2, A3, B0, B1)                                  \
    asm volatile(                                                            \
        "mma.sync.aligned.m16n8k8.row.col.f32.tf32.tf32.f32 "                \
        "{%0,%1,%2,%3}, {%4,%5,%6,%7}, {%8,%9}, {%0,%1,%2,%3};"              \
        : "+f"((d)[0]), "+f"((d)[1]), "+f"((d)[2]), "+f"((d)[3])             \
        : "r"(__float_as_uint(A0)), "r"(__float_as_uint(A1)),                \
          "r"(__float_as_uint(A2)), "r"(__float_as_uint(A3)),                \
          "r"(__float_as_uint(B0)), "r"(__float_as_uint(B1)))

// ---------------------------------------------------------------- GEMM
// C = alpha * A(MxK) * B^T.  A ALWAYS raw fp32 (in-register tf32 split).
// BHL=1: B pre-split hl float2 [n][k].  BHL=0: B raw fp32.
// NMMA: 1 = ah*bh; 2 = + ah*bl (no A-lo needed); 3 = + al*bh.
// BK=16, 8 warps (MW x NW). Multistage cp.async, ONE barrier per iter.
template<int BM, int BN, int MW, int NW, bool BHL, int NMMA, int PIPE>
__global__ __launch_bounds__(256) void mma_gemm(
    const float* __restrict__ Ap,  int lda, long sAb, long sAh,
    const void* __restrict__ Bp,   int ldb, long sBb, long sBh,
    float* __restrict__ Cp,        int ldc, long sCb, long sCh,
    int K, float alpha)
{
    constexpr int BK = 16;
    constexpr int WM = BM / MW, WN = BN / NW;
    constexpr int MT = WM / 16, NT = WN / 8;
    constexpr int RSA = 20;                      // raw: 16 floats + pad
    constexpr int RSB = BHL ? 40 : 20;
    constexpr int ABYT = BM * RSA * 4;
    constexpr int BBYT = BN * RSB * 4;
    constexpr int STAGE = ABYT + BBYT;
    constexpr int NAC = BM / 64;                 // 16B chunks/thread (A raw)
    constexpr int NBC = BHL ? (BN / 32) : (BN / 64);

    extern __shared__ float sm[];
    const uint32_t sbase = smem_u32(sm);

    const int tid  = threadIdx.x;
    const int wid  = tid >> 5;
    const int lane = tid & 31;
    const int z = blockIdx.z, zb = z / Hc, zh = z % Hc;

    const float*  Ar = Ap + zb * sAb + zh * sAh;
    const float*  Br = (const float*)Bp  + (BHL ? 0 : (zb * sBb + zh * sBh));
    const float2* Bh = (const float2*)Bp + (BHL ? (zb * sBb + zh * sBh) : 0);

    const int m0 = blockIdx.y * BM;
    const int n0 = blockIdx.x * BN;
    const int wm = (wid / NW) * WM;
    const int wn = (wid % NW) * WN;

    float acc[MT][NT][4] = {};

    auto issue = [&](int tile, int buf) {
        const int k0 = tile * BK;
        const uint32_t uA = sbase + buf * STAGE;
        const uint32_t uB = uA + ABYT;
#pragma unroll
        for (int v = 0; v < NAC; v++) {
            int t = tid + v * 256;
            int row = t >> 2, cv = t & 3;
            CP_ASYNC16(uA + row * (RSA * 4) + cv * 16,
                       Ar + (long)(m0 + row) * lda + k0 + cv * 4);
        }
        if constexpr (BHL) {
#pragma unroll
            for (int v = 0; v < NBC; v++) {
                int t = tid + v * 256;
                int row = t >> 3, cv = t & 7;
                CP_ASYNC16(uB + row * (RSB * 4) + cv * 16,
                           Bh + (long)(n0 + row) * ldb + k0 + cv * 2);
            }
        } else {
#pragma unroll
            for (int v = 0; v < NBC; v++) {
                int t = tid + v * 256;
                int row = t >> 2, cv = t & 3;
                CP_ASYNC16(uB + row * (RSB * 4) + cv * 16,
                           Br + (long)(n0 + row) * ldb + k0 + cv * 4);
            }
        }
    };

    auto compute = [&](int buf) {
        const float* sA = sm + (buf * STAGE) / 4;
        const float* sB = sA + ABYT / 4;
        const int mlo = wm + (lane >> 2);
        const int nlo = wn + (lane >> 2);
#pragma unroll
        for (int ks = 0; ks < 2; ks++) {
            const int kb = ks * 8 + (lane & 3);
            float b0h[NT], b0l[NT], b1h[NT], b1l[NT];
#pragma unroll
            for (int nt = 0; nt < NT; nt++) {
                if constexpr (BHL) {
                    const float* bp = sB + (nlo + nt * 8) * RSB + kb * 2;
                    float2 p0 = *(const float2*)(bp);
                    float2 p1 = *(const float2*)(bp + 8);
                    b0h[nt] = p0.x; b0l[nt] = p0.y;
                    b1h[nt] = p1.x; b1l[nt] = p1.y;
                } else {
                    const float* bp = sB + (nlo + nt * 8) * RSB + kb;
                    float x0 = bp[0], x1 = bp[4];
                    b0h[nt] = to_tf32(x0);
                    b1h[nt] = to_tf32(x1);
                    if constexpr (NMMA >= 2) {
                        b0l[nt] = to_tf32(x0 - b0h[nt]);
                        b1l[nt] = to_tf32(x1 - b1h[nt]);
                    }
                }
            }
#pragma unroll
            for (int mt = 0; mt < MT; mt++) {
                const float* ap = sA + (mlo + mt * 16) * RSA + kb;
                float x0 = ap[0], x2 = ap[4];
                float x1 = ap[8 * RSA], x3 = ap[8 * RSA + 4];
                float a0h = to_tf32(x0);
                float a1h = to_tf32(x1);
                float a2h = to_tf32(x2);
                float a3h = to_tf32(x3);
                float a0l, a1l, a2l, a3l;
                if constexpr (NMMA == 3) {
                    a0l = to_tf32(x0 - a0h);
                    a1l = to_tf32(x1 - a1h);
                    a2l = to_tf32(x2 - a2h);
                    a3l = to_tf32(x3 - a3h);
                }
#pragma unroll
                for (int nt = 0; nt < NT; nt++) {
                    MMA_TF32(acc[mt][nt], a0h, a1h, a2h, a3h, b0h[nt], b1h[nt]);
                    if constexpr (NMMA >= 2)
                        MMA_TF32(acc[mt][nt], a0h, a1h, a2h, a3h, b0l[nt], b1l[nt]);
                    if constexpr (NMMA == 3)
                        MMA_TF32(acc[mt][nt], a0l, a1l, a2l, a3l, b0h[nt], b1h[nt]);
                }
            }
        }
    };

    // ---- multistage mainloop: ONE barrier per iteration ----------------
    const int ntile = K / BK;
#pragma unroll
    for (int s = 0; s < PIPE - 1; s++) {
        issue(s, s);
        CP_COMMIT();
    }
    for (int i = 0; i < ntile; i++) {
        CP_WAIT(PIPE - 2);
        __syncthreads();
        compute(i % PIPE);
        const int nx = i + PIPE - 1;
        if (nx < ntile) issue(nx, nx % PIPE);
        CP_COMMIT();
    }

    // ---- epilogue: raw fp32 stores -------------------------------------
    float* C = Cp + zb * sCb + zh * sCh;
#pragma unroll
    for (int mt = 0; mt < MT; mt++) {
        const int row = m0 + wm + mt * 16 + (lane >> 2);
#pragma unroll
        for (int nt = 0; nt < NT; nt++) {
            const int col = n0 + wn + nt * 8 + (lane & 3) * 2;
            float2 o;
            o.x = alpha * acc[mt][nt][0];
            o.y = alpha * acc[mt][nt][1];
            *(float2*)(C + (long)row * ldc + col) = o;
            o.x = alpha * acc[mt][nt][2];
            o.y = alpha * acc[mt][nt][3];
            *(float2*)(C + (long)(row + 8) * ldc + col) = o;
        }
    }
}

// ---------------------------------------------------------------- transpose (raw)
__global__ __launch_bounds__(256) void transpose_kernel(
    const float* __restrict__ in, long sInb, long sInh, int ldin,
    float* __restrict__ out, long sOut, int ldout)
{
    __shared__ float t[32][33];
    const int z = blockIdx.z, zb = z / Hc, zh = z % Hc;
    in  += zb * sInb + zh * sInh;
    out += (long)z * sOut;
    const int c0 = blockIdx.x * 32, r0 = blockIdx.y * 32;
    const int tx = threadIdx.x & 31, ty = threadIdx.x >> 5;
#pragma unroll
    for (int j = 0; j < 32; j += 8)
        t[ty + j][tx] = in[(long)(r0 + ty + j) * ldin + c0 + tx];
    __syncthreads();
#pragma unroll
    for (int j = 0; j < 32; j += 8)
        out[(long)(c0 + ty + j) * ldout + r0 + tx] = t[tx][ty + j];
}

// ---------------------------------------------------------------- transpose + split (weights)
__global__ __launch_bounds__(256) void transpose_split_kernel(
    const float* __restrict__ in, int ldin,
    float2* __restrict__ out, int ldout)
{
    __shared__ float t[32][33];
    const int c0 = blockIdx.x * 32, r0 = blockIdx.y * 32;
    const int tx = threadIdx.x & 31, ty = threadIdx.x >> 5;
#pragma unroll
    for (int j = 0; j < 32; j += 8)
        t[ty + j][tx] = in[(long)(r0 + ty + j) * ldin + c0 + tx];
    __syncthreads();
#pragma unroll
    for (int j = 0; j < 32; j += 8) {
        float v = t[tx][ty + j];
        float hi = to_tf32(v);
        out[(long)(c0 + ty + j) * ldout + r0 + tx] = make_float2(hi, to_tf32(v - hi));
    }
}

// ---------------------------------------------------------------- softmax (R6/R8/R12 proven — FROZEN)
__global__ __launch_bounds__(256) void softmax_mean_kernel(
    const float* __restrict__ mask, float* __restrict__ attn_out)
{
    const int bq   = blockIdx.x;
    const int b    = bq >> 11;
    const int q    = bq & 2047;
    const int tid  = threadIdx.x;
    const int lane = tid & 31;
    const int warp = tid >> 5;

    __shared__ float red[8];

    float mrow[8];
#pragma unroll
    for (int t = 0; t < 8; t++)
        mrow[t] = mask[(long)q * Sc + tid + t * 256];

    float macc[8] = {0.f, 0.f, 0.f, 0.f, 0.f, 0.f, 0.f, 0.f};

    for (int h = 0; h < Hc; h++) {
        float* p = g_scores + ((long)(b * Hc + h) * Sc + q) * Sc;
        float v[8];
        float mx = -INFINITY;
#pragma unroll
        for (int t = 0; t < 8; t++) {
            v[t] = p[tid + t * 256] + mrow[t];
            mx = fmaxf(mx, v[t]);
        }
#pragma unroll
        for (int o = 16; o > 0; o >>= 1)
            mx = fmaxf(mx, __shfl_xor_sync(0xffffffffu, mx, o));
        if (lane == 0) red[warp] = mx;
        __syncthreads();
        float bm = red[0];
#pragma unroll
        for (int w = 1; w < 8; w++) bm = fmaxf(bm, red[w]);
        __syncthreads();

        float s = 0.f;
#pragma unroll
        for (int t = 0; t < 8; t++) {
            v[t] = __expf(v[t] - bm);
            s += v[t];
        }
#pragma unroll
        for (int o = 16; o > 0; o >>= 1)
            s += __shfl_xor_sync(0xffffffffu, s, o);
        if (lane == 0) red[warp] = s;
        __syncthreads();
        float tot = 0.f;
#pragma unroll
        for (int w = 0; w < 8; w++) tot += red[w];
        __syncthreads();

        const float inv = 1.0f / tot;
#pragma unroll
        for (int t = 0; t < 8; t++) {
            float pe = v[t] * inv;
            p[tid + t * 256] = pe;
            macc[t] += pe;
        }
    }

#pragma unroll
    for (int t = 0; t < 8; t++)
        attn_out[(long)bq * Sc + tid + t * 256] = macc[t] * 0.125f;
}

// ---------------------------------------------------------------- launcher
extern "C" void kernel_launch(void* const* d_in, const int* in_sizes, int n_in,
                              void* d_out, int out_size)
{
    (void)in_sizes; (void)n_in; (void)out_size;

    const float* Zq   = (const float*)d_in[0];
    const float* Zkv  = (const float*)d_in[1];
    const float* mask = (const float*)d_in[2];
    const float* Wqkv = (const float*)d_in[3];
    const float* Wout = (const float*)d_in[4];

    float* out      = (float*)d_out;
    float* attn_out = out + QKV_N;

    float2 *gWT, *gWoT;
    float  *gQr, *gKr, *gV, *gVt, *gCtx, *gS;
    cudaGetSymbolAddress((void**)&gWT,  g_WT_hl);
    cudaGetSymbolAddress((void**)&gWoT, g_WoT_hl);
    cudaGetSymbolAddress((void**)&gQr,  g_Qr);
    cudaGetSymbolAddress((void**)&gKr,  g_Kr);
    cudaGetSymbolAddress((void**)&gV,   g_V);
    cudaGetSymbolAddress((void**)&gVt,  g_Vt);
    cudaGetSymbolAddress((void**)&gCtx, g_ctx);
    cudaGetSymbolAddress((void**)&gS,   g_scores);

    // smem per instantiation: PIPE * (BM*RSA + BN*RSB) * 4
    constexpr int SM_PROJ = 3 * (64 * 20 + 128 * 40) * 4;    // 76800 (PIPE=3, 2 CTA/SM)
    constexpr int SM_SCR  = 3 * (128 * 20 + 128 * 20) * 4;   // 61440
    constexpr int SM_PV   = 3 * (256 * 20 + 64 * 20) * 4;    // 76800
    cudaFuncSetAttribute(mma_gemm<64, 128, 4, 2, true, 3, 3>,
                         cudaFuncAttributeMaxDynamicSharedMemorySize, SM_PROJ);
    cudaFuncSetAttribute(mma_gemm<64, 128, 4, 2, true, 2, 3>,
                         cudaFuncAttributeMaxDynamicSharedMemorySize, SM_PROJ);
    cudaFuncSetAttribute(mma_gemm<128, 128, 2, 4, false, 3, 3>,
                         cudaFuncAttributeMaxDynamicSharedMemorySize, SM_SCR);
    cudaFuncSetAttribute(mma_gemm<256, 64, 8, 1, false, 1, 3>,
                         cudaFuncAttributeMaxDynamicSharedMemorySize, SM_PV);

    dim3 blk(256);

    // 0) weight prep only (inputs consumed raw)
    transpose_split_kernel<<<dim3(1536 / 32, 512 / 32, 1), blk>>>(
        Wqkv, 3 * Dc, gWT, Dc);
    transpose_split_kernel<<<dim3(512 / 32, 512 / 32, 1), blk>>>(
        Wout, Dc, gWoT, Dc);

    // 1-3) projections: raw Z @ W^T hl, K=512. MW=4/NW=2: halves redundant
    //      A-splits (B is pre-split; fragment load shifts alu -> LDS).
    {
        dim3 g(Dc / 128, (Bc * Sc) / 64, 1);
        mma_gemm<64, 128, 4, 2, true, 3, 3><<<g, blk, SM_PROJ>>>(
            Zq,  Dc, 0, 0,  gWT,               Dc, 0, 0,  gQr, Dc, 0, 0,  Dc, 1.0f);
        mma_gemm<64, 128, 4, 2, true, 3, 3><<<g, blk, SM_PROJ>>>(
            Zkv, Dc, 0, 0,  gWT + Dc * Dc,     Dc, 0, 0,  gKr, Dc, 0, 0,  Dc, 1.0f);
        mma_gemm<64, 128, 4, 2, true, 2, 3><<<g, blk, SM_PROJ>>>(
            Zkv, Dc, 0, 0,  gWT + 2 * Dc * Dc, Dc, 0, 0,  gV,  Dc, 0, 0,  Dc, 1.0f);
    }

    // 3b) V transpose per (b,h): [s,dk] -> [dk,s] raw
    transpose_kernel<<<dim3(DKc / 32, Sc / 32, Bc * Hc), blk>>>(
        gV, (long)Sc * Dc, DKc, Dc, gVt, (long)DKc * Sc, Sc);

    // 4) scores = 0.125 * Q @ K^T per (b,h): raw operands, in-reg x3
    {
        dim3 g(Sc / 128, Sc / 128, Bc * Hc);
        mma_gemm<128, 128, 2, 4, false, 3, 3><<<g, blk, SM_SCR>>>(
            gQr, Dc, (long)Sc * Dc, DKc,
            gKr, Dc, (long)Sc * Dc, DKc,
            gS, Sc, (long)Hc * Sc * Sc, (long)Sc * Sc,
            DKc, 0.125f);
    }

    // 5) softmax (+mask) in-place + head-mean (frozen R12 version)
    softmax_mean_kernel<<<Bc * Sc, blk>>>(mask, attn_out);

    // 6) ctx = P @ V per (b,h): raw P x raw Vt, x1 (hi*hi)
    {
        dim3 g(1, Sc / 256, Bc * Hc);
        mma_gemm<256, 64, 8, 1, false, 1, 3><<<g, blk, SM_PV>>>(
            gS,  Sc, (long)Hc * Sc * Sc, (long)Sc * Sc,
            gVt, Sc, (long)Hc * DKc * Sc, (long)DKc * Sc,
            gCtx, Dc, (long)Sc * Dc, DKc,
            Sc, 1.0f);
    }

    // 7) out = ctx @ Wout: raw ctx @ WoT hl, K=512, x2, MW=4/NW=2
    {
        dim3 g(Dc / 128, (Bc * Sc) / 64, 1);
        mma_gemm<64, 128, 4, 2, true, 2, 3><<<g, blk, SM_PROJ>>>(
            gCtx, Dc, 0, 0,  gWoT, Dc, 0, 0,  out, Dc, 0, 0,  Dc, 1.0f);
    }
}

// round 15
// speedup vs baseline: 1.1418x; 1.1237x over previous
#include <cuda_runtime.h>
#include <cuda_fp16.h>
#include <math.h>
#include <stdint.h>

// ---------------------------------------------------------------- constants
constexpr int  Bc  = 4;
constexpr int  Sc  = 2048;
constexpr int  Dc  = 512;
constexpr int  Hc  = 8;
constexpr int  DKc = 64;

constexpr long QKV_N   = (long)Bc * Sc * Dc;
constexpr long SCORE_N = (long)Bc * Hc * Sc * Sc;

__device__ float2 g_WT_hl[3 * Dc * Dc];     // Wqkv^T [1536][512] hi/lo
__device__ float2 g_WoT_hl[Dc * Dc];        // Wout^T [512][512] hi/lo
__device__ float  g_Qr[QKV_N];              // raw fp32
__device__ float  g_Kr[QKV_N];
__device__ float  g_V[QKV_N];
__device__ __half g_Vt16[QKV_N];            // per (b,h): [dk=64][s=2048] fp16
__device__ float  g_ctx[QKV_N];             // raw fp32
__device__ float  g_scores[SCORE_N];        // raw scores (read by softmax)
__device__ __half g_P16[SCORE_N];           // probabilities, fp16

// ---------------------------------------------------------------- helpers
__device__ __forceinline__ float to_tf32(float x) {
    float y;
    asm("cvt.rna.tf32.f32 %0, %1;" : "=f"(y) : "f"(x));
    return y;
}
__device__ __forceinline__ uint32_t smem_u32(const void* p) {
    uint32_t a;
    asm("{ .reg .u64 t; cvta.to.shared.u64 t, %1; cvt.u32.u64 %0, t; }"
        : "=r"(a) : "l"(p));
    return a;
}

#define CP_ASYNC16(dst, src) \
    asm volatile("cp.async.cg.shared.global [%0], [%1], 16;" \
                 :: "r"(dst), "l"(src) : "memory")
#define CP_COMMIT() asm volatile("cp.async.commit_group;" ::: "memory")
#define CP_WAIT(n)  asm volatile("cp.async.wait_group %0;" :: "n"(n) : "memory")

#define MMA_TF32(d, A0, A1, A2, A3, B0, B1)                                  \
    asm volatile(                                                            \
        "mma.sync.aligned.m16n8k8.row.col.f32.tf32.tf32.f32 "                \
        "{%0,%1,%2,%3}, {%4,%5,%6,%7}, {%8,%9}, {%0,%1,%2,%3};"              \
        : "+f"((d)[0]), "+f"((d)[1]), "+f"((d)[2]), "+f"((d)[3])             \
        : "r"(__float_as_uint(A0)), "r"(__float_as_uint(A1)),                \
          "r"(__float_as_uint(A2)), "r"(__float_as_uint(A3)),                \
          "r"(__float_as_uint(B0)), "r"(__float_as_uint(B1)))

#define MMA_F16(d, A0, A1, A2, A3, B0, B1)                                   \
    asm volatile(                                                            \
        "mma.sync.aligned.m16n8k16.row.col.f32.f16.f16.f32 "                 \
        "{%0,%1,%2,%3}, {%4,%5,%6,%7}, {%8,%9}, {%0,%1,%2,%3};"              \
        : "+f"((d)[0]), "+f"((d)[1]), "+f"((d)[2]), "+f"((d)[3])             \
        : "r"(A0), "r"(A1), "r"(A2), "r"(A3), "r"(B0), "r"(B1))

// ---------------------------------------------------------------- GEMM (tf32 path)
// C = alpha * A(MxK) * B^T.  A raw fp32 (in-register tf32 split).
// BHL=1: B pre-split hl float2 [n][k].  BHL=0: B raw fp32.
// NMMA: 1 = ah*bh; 2 = + ah*bl; 3 = + al*bh.
template<int BM, int BN, int MW, int NW, bool BHL, int NMMA, int PIPE>
__global__ __launch_bounds__(256) void mma_gemm(
    const float* __restrict__ Ap,  int lda, long sAb, long sAh,
    const void* __restrict__ Bp,   int ldb, long sBb, long sBh,
    float* __restrict__ Cp,        int ldc, long sCb, long sCh,
    int K, float alpha)
{
    constexpr int BK = 16;
    constexpr int WM = BM / MW, WN = BN / NW;
    constexpr int MT = WM / 16, NT = WN / 8;
    constexpr int RSA = 20;
    constexpr int RSB = BHL ? 40 : 20;
    constexpr int ABYT = BM * RSA * 4;
    constexpr int BBYT = BN * RSB * 4;
    constexpr int STAGE = ABYT + BBYT;
    constexpr int NAC = BM / 64;
    constexpr int NBC = BHL ? (BN / 32) : (BN / 64);

    extern __shared__ float sm[];
    const uint32_t sbase = smem_u32(sm);

    const int tid  = threadIdx.x;
    const int wid  = tid >> 5;
    const int lane = tid & 31;
    const int z = blockIdx.z, zb = z / Hc, zh = z % Hc;

    const float*  Ar = Ap + zb * sAb + zh * sAh;
    const float*  Br = (const float*)Bp  + (BHL ? 0 : (zb * sBb + zh * sBh));
    const float2* Bh = (const float2*)Bp + (BHL ? (zb * sBb + zh * sBh) : 0);

    const int m0 = blockIdx.y * BM;
    const int n0 = blockIdx.x * BN;
    const int wm = (wid / NW) * WM;
    const int wn = (wid % NW) * WN;

    float acc[MT][NT][4] = {};

    auto issue = [&](int tile, int buf) {
        const int k0 = tile * BK;
        const uint32_t uA = sbase + buf * STAGE;
        const uint32_t uB = uA + ABYT;
#pragma unroll
        for (int v = 0; v < NAC; v++) {
            int t = tid + v * 256;
            int row = t >> 2, cv = t & 3;
            CP_ASYNC16(uA + row * (RSA * 4) + cv * 16,
                       Ar + (long)(m0 + row) * lda + k0 + cv * 4);
        }
        if constexpr (BHL) {
#pragma unroll
            for (int v = 0; v < NBC; v++) {
                int t = tid + v * 256;
                int row = t >> 3, cv = t & 7;
                CP_ASYNC16(uB + row * (RSB * 4) + cv * 16,
                           Bh + (long)(n0 + row) * ldb + k0 + cv * 2);
            }
        } else {
#pragma unroll
            for (int v = 0; v < NBC; v++) {
                int t = tid + v * 256;
                int row = t >> 2, cv = t & 3;
                CP_ASYNC16(uB + row * (RSB * 4) + cv * 16,
                           Br + (long)(n0 + row) * ldb + k0 + cv * 4);
            }
        }
    };

    auto compute = [&](int buf) {
        const float* sA = sm + (buf * STAGE) / 4;
        const float* sB = sA + ABYT / 4;
        const int mlo = wm + (lane >> 2);
        const int nlo = wn + (lane >> 2);
#pragma unroll
        for (int ks = 0; ks < 2; ks++) {
            const int kb = ks * 8 + (lane & 3);
            float b0h[NT], b0l[NT], b1h[NT], b1l[NT];
#pragma unroll
            for (int nt = 0; nt < NT; nt++) {
                if constexpr (BHL) {
                    const float* bp = sB + (nlo + nt * 8) * RSB + kb * 2;
                    float2 p0 = *(const float2*)(bp);
                    float2 p1 = *(const float2*)(bp + 8);
                    b0h[nt] = p0.x; b0l[nt] = p0.y;
                    b1h[nt] = p1.x; b1l[nt] = p1.y;
                } else {
                    const float* bp = sB + (nlo + nt * 8) * RSB + kb;
                    float x0 = bp[0], x1 = bp[4];
                    b0h[nt] = to_tf32(x0);
                    b1h[nt] = to_tf32(x1);
                    if constexpr (NMMA >= 2) {
                        b0l[nt] = to_tf32(x0 - b0h[nt]);
                        b1l[nt] = to_tf32(x1 - b1h[nt]);
                    }
                }
            }
#pragma unroll
            for (int mt = 0; mt < MT; mt++) {
                const float* ap = sA + (mlo + mt * 16) * RSA + kb;
                float x0 = ap[0], x2 = ap[4];
                float x1 = ap[8 * RSA], x3 = ap[8 * RSA + 4];
                float a0h = to_tf32(x0);
                float a1h = to_tf32(x1);
                float a2h = to_tf32(x2);
                float a3h = to_tf32(x3);
                float a0l, a1l, a2l, a3l;
                if constexpr (NMMA == 3) {
                    a0l = to_tf32(x0 - a0h);
                    a1l = to_tf32(x1 - a1h);
                    a2l = to_tf32(x2 - a2h);
                    a3l = to_tf32(x3 - a3h);
                }
#pragma unroll
                for (int nt = 0; nt < NT; nt++) {
                    MMA_TF32(acc[mt][nt], a0h, a1h, a2h, a3h, b0h[nt], b1h[nt]);
                    if constexpr (NMMA >= 2)
                        MMA_TF32(acc[mt][nt], a0h, a1h, a2h, a3h, b0l[nt], b1l[nt]);
                    if constexpr (NMMA == 3)
                        MMA_TF32(acc[mt][nt], a0l, a1l, a2l, a3l, b0h[nt], b1h[nt]);
                }
            }
        }
    };

    const int ntile = K / BK;
#pragma unroll
    for (int s = 0; s < PIPE - 1; s++) {
        issue(s, s);
        CP_COMMIT();
    }
    for (int i = 0; i < ntile; i++) {
        CP_WAIT(PIPE - 2);
        __syncthreads();
        compute(i % PIPE);
        const int nx = i + PIPE - 1;
        if (nx < ntile) issue(nx, nx % PIPE);
        CP_COMMIT();
    }

    float* C = Cp + zb * sCb + zh * sCh;
#pragma unroll
    for (int mt = 0; mt < MT; mt++) {
        const int row = m0 + wm + mt * 16 + (lane >> 2);
#pragma unroll
        for (int nt = 0; nt < NT; nt++) {
            const int col = n0 + wn + nt * 8 + (lane & 3) * 2;
            float2 o;
            o.x = alpha * acc[mt][nt][0];
            o.y = alpha * acc[mt][nt][1];
            *(float2*)(C + (long)row * ldc + col) = o;
            o.x = alpha * acc[mt][nt][2];
            o.y = alpha * acc[mt][nt][3];
            *(float2*)(C + (long)(row + 8) * ldc + col) = o;
        }
    }
}

// ---------------------------------------------------------------- PV fp16 GEMM
// ctx = P(fp16)[2048 x 2048] @ Vt(fp16)^T[64 x 2048], fp32 accum.
// BM=256, BN=64, BK=32, 8 warps M-stacked (MT=2, NT=8). m16n8k16.
__global__ __launch_bounds__(256) void pv_fp16_kernel(
    const __half* __restrict__ Pp, const __half* __restrict__ Vp,
    float* __restrict__ Cp)
{
    constexpr int BM = 256, BN = 64, BK = 32;
    constexpr int RS  = 40;                      // halves per row (32 + 8 pad)
    constexpr int ABYT = BM * RS * 2;            // 20480
    constexpr int BBYT = BN * RS * 2;            // 5120
    constexpr int STAGE = ABYT + BBYT;           // 25600
    constexpr int PIPE = 3;
    constexpr int MT = 2, NT = 8;

    extern __shared__ char smc[];
    const uint32_t sbase = smem_u32(smc);

    const int tid  = threadIdx.x;
    const int wid  = tid >> 5;
    const int lane = tid & 31;
    const int z = blockIdx.z;                    // bh index

    const __half* Ar = Pp + (long)z * Sc * Sc;           // [2048][2048]
    const __half* Br = Vp + (long)z * DKc * Sc;          // [64][2048]
    float* C = Cp + (long)(z / Hc) * Sc * Dc + (z % Hc) * DKc;

    const int m0 = blockIdx.y * BM;
    const int wm = wid * 32;                     // MW=8

    float acc[MT][NT][4] = {};

    auto issue = [&](int tile, int buf) {
        const int k0 = tile * BK;
        const uint32_t uA = sbase + buf * STAGE;
        const uint32_t uB = uA + ABYT;
#pragma unroll
        for (int v = 0; v < 4; v++) {            // 1024 chunks A
            int t = tid + v * 256;
            int row = t >> 2, cv = t & 3;
            CP_ASYNC16(uA + row * (RS * 2) + cv * 16,
                       Ar + (long)(m0 + row) * Sc + k0 + cv * 8);
        }
        {                                         // 256 chunks B
            int row = tid >> 2, cv = tid & 3;
            CP_ASYNC16(uB + row * (RS * 2) + cv * 16,
                       Br + (long)row * Sc + k0 + cv * 8);
        }
    };

    auto compute = [&](int buf) {
        const __half* sA = (const __half*)(smc + buf * STAGE);
        const __half* sB = (const __half*)(smc + buf * STAGE + ABYT);
        const int r4 = lane >> 2;
        const int c2 = (lane & 3) * 2;
#pragma unroll
        for (int kc = 0; kc < 2; kc++) {
            const int kb = kc * 16 + c2;
            uint32_t b0[NT], b1[NT];
#pragma unroll
            for (int nt = 0; nt < NT; nt++) {
                const __half* bp = sB + (nt * 8 + r4) * RS + kb;
                b0[nt] = *(const uint32_t*)(bp);
                b1[nt] = *(const uint32_t*)(bp + 8);
            }
#pragma unroll
            for (int mt = 0; mt < MT; mt++) {
                const __half* ap = sA + (wm + mt * 16 + r4) * RS + kb;
                uint32_t a0 = *(const uint32_t*)(ap);
                uint32_t a1 = *(const uint32_t*)(ap + 8 * RS);
                uint32_t a2 = *(const uint32_t*)(ap + 8);
                uint32_t a3 = *(const uint32_t*)(ap + 8 * RS + 8);
#pragma unroll
                for (int nt = 0; nt < NT; nt++)
                    MMA_F16(acc[mt][nt], a0, a1, a2, a3, b0[nt], b1[nt]);
            }
        }
    };

    const int ntile = Sc / BK;                   // 64
#pragma unroll
    for (int s = 0; s < PIPE - 1; s++) {
        issue(s, s);
        CP_COMMIT();
    }
    for (int i = 0; i < ntile; i++) {
        CP_WAIT(PIPE - 2);
        __syncthreads();
        compute(i % PIPE);
        const int nx = i + PIPE - 1;
        if (nx < ntile) issue(nx, nx % PIPE);
        CP_COMMIT();
    }

#pragma unroll
    for (int mt = 0; mt < MT; mt++) {
        const int row = m0 + wm + mt * 16 + (lane >> 2);
#pragma unroll
        for (int nt = 0; nt < NT; nt++) {
            const int col = nt * 8 + (lane & 3) * 2;
            float2 o;
            o.x = acc[mt][nt][0];
            o.y = acc[mt][nt][1];
            *(float2*)(C + (long)row * Dc + col) = o;
            o.x = acc[mt][nt][2];
            o.y = acc[mt][nt][3];
            *(float2*)(C + (long)(row + 8) * Dc + col) = o;
        }
    }
}

// ---------------------------------------------------------------- transpose -> fp16
__global__ __launch_bounds__(256) void transpose_h16_kernel(
    const float* __restrict__ in, long sInb, long sInh, int ldin,
    __half* __restrict__ out, long sOut, int ldout)
{
    __shared__ float t[32][33];
    const int z = blockIdx.z, zb = z / Hc, zh = z % Hc;
    in  += zb * sInb + zh * sInh;
    out += (long)z * sOut;
    const int c0 = blockIdx.x * 32, r0 = blockIdx.y * 32;
    const int tx = threadIdx.x & 31, ty = threadIdx.x >> 5;
#pragma unroll
    for (int j = 0; j < 32; j += 8)
        t[ty + j][tx] = in[(long)(r0 + ty + j) * ldin + c0 + tx];
    __syncthreads();
#pragma unroll
    for (int j = 0; j < 32; j += 8)
        out[(long)(c0 + ty + j) * ldout + r0 + tx] = __float2half(t[tx][ty + j]);
}

// ---------------------------------------------------------------- transpose + split (weights)
__global__ __launch_bounds__(256) void transpose_split_kernel(
    const float* __restrict__ in, int ldin,
    float2* __restrict__ out, int ldout)
{
    __shared__ float t[32][33];
    const int c0 = blockIdx.x * 32, r0 = blockIdx.y * 32;
    const int tx = threadIdx.x & 31, ty = threadIdx.x >> 5;
#pragma unroll
    for (int j = 0; j < 32; j += 8)
        t[ty + j][tx] = in[(long)(r0 + ty + j) * ldin + c0 + tx];
    __syncthreads();
#pragma unroll
    for (int j = 0; j < 32; j += 8) {
        float v = t[tx][ty + j];
        float hi = to_tf32(v);
        out[(long)(c0 + ty + j) * ldout + r0 + tx] = make_float2(hi, to_tf32(v - hi));
    }
}

// ---------------------------------------------------------------- softmax (frozen structure; P written fp16)
__global__ __launch_bounds__(256) void softmax_mean_kernel(
    const float* __restrict__ mask, float* __restrict__ attn_out)
{
    const int bq   = blockIdx.x;
    const int b    = bq >> 11;
    const int q    = bq & 2047;
    const int tid  = threadIdx.x;
    const int lane = tid & 31;
    const int warp = tid >> 5;

    __shared__ float red[8];

    float mrow[8];
#pragma unroll
    for (int t = 0; t < 8; t++)
        mrow[t] = mask[(long)q * Sc + tid + t * 256];

    float macc[8] = {0.f, 0.f, 0.f, 0.f, 0.f, 0.f, 0.f, 0.f};

    for (int h = 0; h < Hc; h++) {
        const float* p = g_scores + ((long)(b * Hc + h) * Sc + q) * Sc;
        __half* p16 = g_P16 + ((long)(b * Hc + h) * Sc + q) * Sc;
        float v[8];
        float mx = -INFINITY;
#pragma unroll
        for (int t = 0; t < 8; t++) {
            v[t] = p[tid + t * 256] + mrow[t];
            mx = fmaxf(mx, v[t]);
        }
#pragma unroll
        for (int o = 16; o > 0; o >>= 1)
            mx = fmaxf(mx, __shfl_xor_sync(0xffffffffu, mx, o));
        if (lane == 0) red[warp] = mx;
        __syncthreads();
        float bm = red[0];
#pragma unroll
        for (int w = 1; w < 8; w++) bm = fmaxf(bm, red[w]);
        __syncthreads();

        float s = 0.f;
#pragma unroll
        for (int t = 0; t < 8; t++) {
            v[t] = __expf(v[t] - bm);
            s += v[t];
        }
#pragma unroll
        for (int o = 16; o > 0; o >>= 1)
            s += __shfl_xor_sync(0xffffffffu, s, o);
        if (lane == 0) red[warp] = s;
        __syncthreads();
        float tot = 0.f;
#pragma unroll
        for (int w = 0; w < 8; w++) tot += red[w];
        __syncthreads();

        const float inv = 1.0f / tot;
#pragma unroll
        for (int t = 0; t < 8; t++) {
            float pe = v[t] * inv;
            p16[tid + t * 256] = __float2half(pe);
            macc[t] += pe;
        }
    }

#pragma unroll
    for (int t = 0; t < 8; t++)
        attn_out[(long)bq * Sc + tid + t * 256] = macc[t] * 0.125f;
}

// ---------------------------------------------------------------- launcher
extern "C" void kernel_launch(void* const* d_in, const int* in_sizes, int n_in,
                              void* d_out, int out_size)
{
    (void)in_sizes; (void)n_in; (void)out_size;

    const float* Zq   = (const float*)d_in[0];
    const float* Zkv  = (const float*)d_in[1];
    const float* mask = (const float*)d_in[2];
    const float* Wqkv = (const float*)d_in[3];
    const float* Wout = (const float*)d_in[4];

    float* out      = (float*)d_out;
    float* attn_out = out + QKV_N;

    float2 *gWT, *gWoT;
    float  *gQr, *gKr, *gV, *gCtx, *gS;
    __half *gVt16, *gP16;
    cudaGetSymbolAddress((void**)&gWT,   g_WT_hl);
    cudaGetSymbolAddress((void**)&gWoT,  g_WoT_hl);
    cudaGetSymbolAddress((void**)&gQr,   g_Qr);
    cudaGetSymbolAddress((void**)&gKr,   g_Kr);
    cudaGetSymbolAddress((void**)&gV,    g_V);
    cudaGetSymbolAddress((void**)&gVt16, g_Vt16);
    cudaGetSymbolAddress((void**)&gCtx,  g_ctx);
    cudaGetSymbolAddress((void**)&gS,    g_scores);
    cudaGetSymbolAddress((void**)&gP16,  g_P16);

    constexpr int SM_PROJ = 3 * (64 * 20 + 128 * 40) * 4;    // 76800
    constexpr int SM_SCR  = 3 * (128 * 20 + 128 * 20) * 4;   // 61440
    constexpr int SM_PV   = 3 * (256 * 40 + 64 * 40) * 2;    // 76800
    cudaFuncSetAttribute(mma_gemm<64, 128, 4, 2, true, 3, 3>,
                         cudaFuncAttributeMaxDynamicSharedMemorySize, SM_PROJ);
    cudaFuncSetAttribute(mma_gemm<64, 128, 4, 2, true, 2, 3>,
                         cudaFuncAttributeMaxDynamicSharedMemorySize, SM_PROJ);
    cudaFuncSetAttribute(mma_gemm<128, 128, 2, 4, false, 3, 3>,
                         cudaFuncAttributeMaxDynamicSharedMemorySize, SM_SCR);
    cudaFuncSetAttribute(pv_fp16_kernel,
                         cudaFuncAttributeMaxDynamicSharedMemorySize, SM_PV);

    dim3 blk(256);

    // 0) weight prep
    transpose_split_kernel<<<dim3(1536 / 32, 512 / 32, 1), blk>>>(
        Wqkv, 3 * Dc, gWT, Dc);
    transpose_split_kernel<<<dim3(512 / 32, 512 / 32, 1), blk>>>(
        Wout, Dc, gWoT, Dc);

    // 1-3) projections (MW=4/NW=2; Q,K x3; V x2)
    {
        dim3 g(Dc / 128, (Bc * Sc) / 64, 1);
        mma_gemm<64, 128, 4, 2, true, 3, 3><<<g, blk, SM_PROJ>>>(
            Zq,  Dc, 0, 0,  gWT,               Dc, 0, 0,  gQr, Dc, 0, 0,  Dc, 1.0f);
        mma_gemm<64, 128, 4, 2, true, 3, 3><<<g, blk, SM_PROJ>>>(
            Zkv, Dc, 0, 0,  gWT + Dc * Dc,     Dc, 0, 0,  gKr, Dc, 0, 0,  Dc, 1.0f);
        mma_gemm<64, 128, 4, 2, true, 2, 3><<<g, blk, SM_PROJ>>>(
            Zkv, Dc, 0, 0,  gWT + 2 * Dc * Dc, Dc, 0, 0,  gV,  Dc, 0, 0,  Dc, 1.0f);
    }

    // 3b) V transpose -> fp16 per (b,h): [s,dk] -> [dk,s]
    transpose_h16_kernel<<<dim3(DKc / 32, Sc / 32, Bc * Hc), blk>>>(
        gV, (long)Sc * Dc, DKc, Dc, gVt16, (long)DKc * Sc, Sc);

    // 4) scores = 0.125 * Q @ K^T per (b,h): raw operands, in-reg x3
    {
        dim3 g(Sc / 128, Sc / 128, Bc * Hc);
        mma_gemm<128, 128, 2, 4, false, 3, 3><<<g, blk, SM_SCR>>>(
            gQr, Dc, (long)Sc * Dc, DKc,
            gKr, Dc, (long)Sc * Dc, DKc,
            gS, Sc, (long)Hc * Sc * Sc, (long)Sc * Sc,
            DKc, 0.125f);
    }

    // 5) softmax (+mask) + head-mean; P written fp16
    softmax_mean_kernel<<<Bc * Sc, blk>>>(mask, attn_out);

    // 6) ctx = P @ V per (b,h): fp16 x fp16, fp32 accum (m16n8k16)
    {
        dim3 g(1, Sc / 256, Bc * Hc);
        pv_fp16_kernel<<<g, blk, SM_PV>>>(gP16, gVt16, gCtx);
    }

    // 7) out = ctx @ Wout: raw ctx @ WoT hl, K=512, x2, MW=4/NW=2
    {
        dim3 g(Dc / 128, (Bc * Sc) / 64, 1);
        mma_gemm<64, 128, 4, 2, true, 2, 3><<<g, blk, SM_PROJ>>>(
            gCtx, Dc, 0, 0,  gWoT, Dc, 0, 0,  out, Dc, 0, 0,  Dc, 1.0f);
    }
}

// round 17
// speedup vs baseline: 1.1749x; 1.0290x over previous
#include <cuda_runtime.h>
#include <cuda_fp16.h>
#include <math.h>
#include <stdint.h>

// ---------------------------------------------------------------- constants
constexpr int  Bc  = 4;
constexpr int  Sc  = 2048;
constexpr int  Dc  = 512;
constexpr int  Hc  = 8;
constexpr int  DKc = 64;

constexpr long QKV_N   = (long)Bc * Sc * Dc;
constexpr long SCORE_N = (long)Bc * Hc * Sc * Sc;

__device__ float2 g_WT_hl[3 * Dc * Dc];     // Wqkv^T [1536][512] hi/lo
__device__ float2 g_WoT_hl[Dc * Dc];        // Wout^T [512][512] hi/lo
__device__ float  g_QKV[3 * QKV_N];         // fused [8192][1536]: Q|K|V
__device__ __half g_Vt16[QKV_N];            // per (b,h): [dk=64][s=2048] fp16
__device__ float  g_ctx[QKV_N];             // raw fp32
__device__ float  g_scores[SCORE_N];        // raw scores (read by softmax)
__device__ __half g_P16[SCORE_N];           // probabilities, fp16

// ---------------------------------------------------------------- helpers
__device__ __forceinline__ float to_tf32(float x) {
    float y;
    asm("cvt.rna.tf32.f32 %0, %1;" : "=f"(y) : "f"(x));
    return y;
}
__device__ __forceinline__ uint32_t smem_u32(const void* p) {
    uint32_t a;
    asm("{ .reg .u64 t; cvta.to.shared.u64 t, %1; cvt.u32.u64 %0, t; }"
        : "=r"(a) : "l"(p));
    return a;
}

#define CP_ASYNC16(dst, src) \
    asm volatile("cp.async.cg.shared.global [%0], [%1], 16;" \
                 :: "r"(dst), "l"(src) : "memory")
#define CP_COMMIT() asm volatile("cp.async.commit_group;" ::: "memory")
#define CP_WAIT(n)  asm volatile("cp.async.wait_group %0;" :: "n"(n) : "memory")

#define MMA_TF32(d, A0, A1, A2, A3, B0, B1)                                  \
    asm volatile(                                                            \
        "mma.sync.aligned.m16n8k8.row.col.f32.tf32.tf32.f32 "                \
        "{%0,%1,%2,%3}, {%4,%5,%6,%7}, {%8,%9}, {%0,%1,%2,%3};"              \
        : "+f"((d)[0]), "+f"((d)[1]), "+f"((d)[2]), "+f"((d)[3])             \
        : "r"(__float_as_uint(A0)), "r"(__float_as_uint(A1)),                \
          "r"(__float_as_uint(A2)), "r"(__float_as_uint(A3)),                \
          "r"(__float_as_uint(B0)), "r"(__float_as_uint(B1)))

#define MMA_F16(d, A0, A1, A2, A3, B0, B1)                                   \
    asm volatile(                                                            \
        "mma.sync.aligned.m16n8k16.row.col.f32.f16.f16.f32 "                 \
        "{%0,%1,%2,%3}, {%4,%5,%6,%7}, {%8,%9}, {%0,%1,%2,%3};"              \
        : "+f"((d)[0]), "+f"((d)[1]), "+f"((d)[2]), "+f"((d)[3])             \
        : "r"(A0), "r"(A1), "r"(A2), "r"(A3), "r"(B0), "r"(B1))

// ---------------------------------------------------------------- GEMM (tf32 path)
// C = alpha * A(MxK) * B^T.  A raw fp32 (in-register tf32 split).
// BHL=1: B pre-split hl float2 [n][k].  BHL=0: B raw fp32.
// NMMA: 1 = ah*bh; 2 = + ah*bl; 3 = + al*bh.
// FQKV: fused QKV mode. A = (n0 < Dc) ? Ap : Ap2; third MMA only if n0 < 2*Dc.
template<int BM, int BN, int MW, int NW, bool BHL, int NMMA, int PIPE, bool FQKV>
__global__ __launch_bounds__(256) void mma_gemm(
    const float* __restrict__ Ap,  const float* __restrict__ Ap2,
    int lda, long sAb, long sAh,
    const void* __restrict__ Bp,   int ldb, long sBb, long sBh,
    float* __restrict__ Cp,        int ldc, long sCb, long sCh,
    int K, float alpha)
{
    constexpr int BK = 16;
    constexpr int WM = BM / MW, WN = BN / NW;
    constexpr int MT = WM / 16, NT = WN / 8;
    constexpr int RSA = 20;
    constexpr int RSB = BHL ? 40 : 20;
    constexpr int ABYT = BM * RSA * 4;
    constexpr int BBYT = BN * RSB * 4;
    constexpr int STAGE = ABYT + BBYT;
    constexpr int NAC = BM / 64;
    constexpr int NBC = BHL ? (BN / 32) : (BN / 64);

    extern __shared__ float sm[];
    const uint32_t sbase = smem_u32(sm);

    const int tid  = threadIdx.x;
    const int wid  = tid >> 5;
    const int lane = tid & 31;
    const int z = blockIdx.z, zb = z / Hc, zh = z % Hc;

    const int m0 = blockIdx.y * BM;
    const int n0 = blockIdx.x * BN;

    const float* Abase = (FQKV && n0 >= Dc) ? Ap2 : Ap;
    const float*  Ar = Abase + zb * sAb + zh * sAh;
    const float*  Br = (const float*)Bp  + (BHL ? 0 : (zb * sBb + zh * sBh));
    const float2* Bh = (const float2*)Bp + (BHL ? (zb * sBb + zh * sBh) : 0);
    const bool third = !FQKV || (n0 < 2 * Dc);   // V columns use x2

    const int wm = (wid / NW) * WM;
    const int wn = (wid % NW) * WN;

    float acc[MT][NT][4] = {};

    auto issue = [&](int tile, int buf) {
        const int k0 = tile * BK;
        const uint32_t uA = sbase + buf * STAGE;
        const uint32_t uB = uA + ABYT;
#pragma unroll
        for (int v = 0; v < NAC; v++) {
            int t = tid + v * 256;
            int row = t >> 2, cv = t & 3;
            CP_ASYNC16(uA + row * (RSA * 4) + cv * 16,
                       Ar + (long)(m0 + row) * lda + k0 + cv * 4);
        }
        if constexpr (BHL) {
#pragma unroll
            for (int v = 0; v < NBC; v++) {
                int t = tid + v * 256;
                int row = t >> 3, cv = t & 7;
                CP_ASYNC16(uB + row * (RSB * 4) + cv * 16,
                           Bh + (long)(n0 + row) * ldb + k0 + cv * 2);
            }
        } else {
#pragma unroll
            for (int v = 0; v < NBC; v++) {
                int t = tid + v * 256;
                int row = t >> 2, cv = t & 3;
                CP_ASYNC16(uB + row * (RSB * 4) + cv * 16,
                           Br + (long)(n0 + row) * ldb + k0 + cv * 4);
            }
        }
    };

    auto compute = [&](int buf) {
        const float* sA = sm + (buf * STAGE) / 4;
        const float* sB = sA + ABYT / 4;
        const int mlo = wm + (lane >> 2);
        const int nlo = wn + (lane >> 2);
#pragma unroll
        for (int ks = 0; ks < 2; ks++) {
            const int kb = ks * 8 + (lane & 3);
            float b0h[NT], b0l[NT], b1h[NT], b1l[NT];
#pragma unroll
            for (int nt = 0; nt < NT; nt++) {
                if constexpr (BHL) {
                    const float* bp = sB + (nlo + nt * 8) * RSB + kb * 2;
                    float2 p0 = *(const float2*)(bp);
                    float2 p1 = *(const float2*)(bp + 8);
                    b0h[nt] = p0.x; b0l[nt] = p0.y;
                    b1h[nt] = p1.x; b1l[nt] = p1.y;
                } else {
                    const float* bp = sB + (nlo + nt * 8) * RSB + kb;
                    float x0 = bp[0], x1 = bp[4];
                    b0h[nt] = to_tf32(x0);
                    b1h[nt] = to_tf32(x1);
                    if constexpr (NMMA >= 2) {
                        b0l[nt] = to_tf32(x0 - b0h[nt]);
                        b1l[nt] = to_tf32(x1 - b1h[nt]);
                    }
                }
            }
#pragma unroll
            for (int mt = 0; mt < MT; mt++) {
                const float* ap = sA + (mlo + mt * 16) * RSA + kb;
                float x0 = ap[0], x2 = ap[4];
                float x1 = ap[8 * RSA], x3 = ap[8 * RSA + 4];
                float a0h = to_tf32(x0);
                float a1h = to_tf32(x1);
                float a2h = to_tf32(x2);
                float a3h = to_tf32(x3);
                float a0l, a1l, a2l, a3l;
                if constexpr (NMMA == 3) {
                    a0l = to_tf32(x0 - a0h);
                    a1l = to_tf32(x1 - a1h);
                    a2l = to_tf32(x2 - a2h);
                    a3l = to_tf32(x3 - a3h);
                }
#pragma unroll
                for (int nt = 0; nt < NT; nt++) {
                    MMA_TF32(acc[mt][nt], a0h, a1h, a2h, a3h, b0h[nt], b1h[nt]);
                    if constexpr (NMMA >= 2)
                        MMA_TF32(acc[mt][nt], a0h, a1h, a2h, a3h, b0l[nt], b1l[nt]);
                    if constexpr (NMMA == 3)
                        if (third)
                            MMA_TF32(acc[mt][nt], a0l, a1l, a2l, a3l, b0h[nt], b1h[nt]);
                }
            }
        }
    };

    const int ntile = K / BK;
#pragma unroll
    for (int s = 0; s < PIPE - 1; s++) {
        issue(s, s);
        CP_COMMIT();
    }
    for (int i = 0; i < ntile; i++) {
        CP_WAIT(PIPE - 2);
        __syncthreads();
        compute(i % PIPE);
        const int nx = i + PIPE - 1;
        if (nx < ntile) issue(nx, nx % PIPE);
        CP_COMMIT();
    }

    float* C = Cp + zb * sCb + zh * sCh;
#pragma unroll
    for (int mt = 0; mt < MT; mt++) {
        const int row = m0 + wm + mt * 16 + (lane >> 2);
#pragma unroll
        for (int nt = 0; nt < NT; nt++) {
            const int col = n0 + wn + nt * 8 + (lane & 3) * 2;
            float2 o;
            o.x = alpha * acc[mt][nt][0];
            o.y = alpha * acc[mt][nt][1];
            *(float2*)(C + (long)row * ldc + col) = o;
            o.x = alpha * acc[mt][nt][2];
            o.y = alpha * acc[mt][nt][3];
            *(float2*)(C + (long)(row + 8) * ldc + col) = o;
        }
    }
}

// ---------------------------------------------------------------- PV fp16 GEMM
__global__ __launch_bounds__(256) void pv_fp16_kernel(
    const __half* __restrict__ Pp, const __half* __restrict__ Vp,
    float* __restrict__ Cp)
{
    constexpr int BM = 256, BN = 64, BK = 32;
    constexpr int RS  = 40;
    constexpr int ABYT = BM * RS * 2;
    constexpr int BBYT = BN * RS * 2;
    constexpr int STAGE = ABYT + BBYT;
    constexpr int PIPE = 3;
    constexpr int MT = 2, NT = 8;

    extern __shared__ char smc[];
    const uint32_t sbase = smem_u32(smc);

    const int tid  = threadIdx.x;
    const int wid  = tid >> 5;
    const int lane = tid & 31;
    const int z = blockIdx.z;

    const __half* Ar = Pp + (long)z * Sc * Sc;
    const __half* Br = Vp + (long)z * DKc * Sc;
    float* C = Cp + (long)(z / Hc) * Sc * Dc + (z % Hc) * DKc;

    const int m0 = blockIdx.y * BM;
    const int wm = wid * 32;

    float acc[MT][NT][4] = {};

    auto issue = [&](int tile, int buf) {
        const int k0 = tile * BK;
        const uint32_t uA = sbase + buf * STAGE;
        const uint32_t uB = uA + ABYT;
#pragma unroll
        for (int v = 0; v < 4; v++) {
            int t = tid + v * 256;
            int row = t >> 2, cv = t & 3;
            CP_ASYNC16(uA + row * (RS * 2) + cv * 16,
                       Ar + (long)(m0 + row) * Sc + k0 + cv * 8);
        }
        {
            int row = tid >> 2, cv = tid & 3;
            CP_ASYNC16(uB + row * (RS * 2) + cv * 16,
                       Br + (long)row * Sc + k0 + cv * 8);
        }
    };

    auto compute = [&](int buf) {
        const __half* sA = (const __half*)(smc + buf * STAGE);
        const __half* sB = (const __half*)(smc + buf * STAGE + ABYT);
        const int r4 = lane >> 2;
        const int c2 = (lane & 3) * 2;
#pragma unroll
        for (int kc = 0; kc < 2; kc++) {
            const int kb = kc * 16 + c2;
            uint32_t b0[NT], b1[NT];
#pragma unroll
            for (int nt = 0; nt < NT; nt++) {
                const __half* bp = sB + (nt * 8 + r4) * RS + kb;
                b0[nt] = *(const uint32_t*)(bp);
                b1[nt] = *(const uint32_t*)(bp + 8);
            }
#pragma unroll
            for (int mt = 0; mt < MT; mt++) {
                const __half* ap = sA + (wm + mt * 16 + r4) * RS + kb;
                uint32_t a0 = *(const uint32_t*)(ap);
                uint32_t a1 = *(const uint32_t*)(ap + 8 * RS);
                uint32_t a2 = *(const uint32_t*)(ap + 8);
                uint32_t a3 = *(const uint32_t*)(ap + 8 * RS + 8);
#pragma unroll
                for (int nt = 0; nt < NT; nt++)
                    MMA_F16(acc[mt][nt], a0, a1, a2, a3, b0[nt], b1[nt]);
            }
        }
    };

    const int ntile = Sc / BK;
#pragma unroll
    for (int s = 0; s < PIPE - 1; s++) {
        issue(s, s);
        CP_COMMIT();
    }
    for (int i = 0; i < ntile; i++) {
        CP_WAIT(PIPE - 2);
        __syncthreads();
        compute(i % PIPE);
        const int nx = i + PIPE - 1;
        if (nx < ntile) issue(nx, nx % PIPE);
        CP_COMMIT();
    }

#pragma unroll
    for (int mt = 0; mt < MT; mt++) {
        const int row = m0 + wm + mt * 16 + (lane >> 2);
#pragma unroll
        for (int nt = 0; nt < NT; nt++) {
            const int col = nt * 8 + (lane & 3) * 2;
            float2 o;
            o.x = acc[mt][nt][0];
            o.y = acc[mt][nt][1];
            *(float2*)(C + (long)row * Dc + col) = o;
            o.x = acc[mt][nt][2];
            o.y = acc[mt][nt][3];
            *(float2*)(C + (long)(row + 8) * Dc + col) = o;
        }
    }
}

// ---------------------------------------------------------------- transpose -> fp16
__global__ __launch_bounds__(256) void transpose_h16_kernel(
    const float* __restrict__ in, long sInb, long sInh, int ldin,
    __half* __restrict__ out, long sOut, int ldout)
{
    __shared__ float t[32][33];
    const int z = blockIdx.z, zb = z / Hc, zh = z % Hc;
    in  += zb * sInb + zh * sInh;
    out += (long)z * sOut;
    const int c0 = blockIdx.x * 32, r0 = blockIdx.y * 32;
    const int tx = threadIdx.x & 31, ty = threadIdx.x >> 5;
#pragma unroll
    for (int j = 0; j < 32; j += 8)
        t[ty + j][tx] = in[(long)(r0 + ty + j) * ldin + c0 + tx];
    __syncthreads();
#pragma unroll
    for (int j = 0; j < 32; j += 8)
        out[(long)(c0 + ty + j) * ldout + r0 + tx] = __float2half(t[tx][ty + j]);
}

// ---------------------------------------------------------------- transpose + split (weights)
__global__ __launch_bounds__(256) void transpose_split_kernel(
    const float* __restrict__ in, int ldin,
    float2* __restrict__ out, int ldout)
{
    __shared__ float t[32][33];
    const int c0 = blockIdx.x * 32, r0 = blockIdx.y * 32;
    const int tx = threadIdx.x & 31, ty = threadIdx.x >> 5;
#pragma unroll
    for (int j = 0; j < 32; j += 8)
        t[ty + j][tx] = in[(long)(r0 + ty + j) * ldin + c0 + tx];
    __syncthreads();
#pragma unroll
    for (int j = 0; j < 32; j += 8) {
        float v = t[tx][ty + j];
        float hi = to_tf32(v);
        out[(long)(c0 + ty + j) * ldout + r0 + tx] = make_float2(hi, to_tf32(v - hi));
    }
}

// ---------------------------------------------------------------- softmax
// Frozen structure + next-head score prefetch (latency overlap only).
__global__ __launch_bounds__(256) void softmax_mean_kernel(
    const float* __restrict__ mask, float* __restrict__ attn_out)
{
    const int bq   = blockIdx.x;
    const int b    = bq >> 11;
    const int q    = bq & 2047;
    const int tid  = threadIdx.x;
    const int lane = tid & 31;
    const int warp = tid >> 5;

    __shared__ float red[8];

    float mrow[8];
#pragma unroll
    for (int t = 0; t < 8; t++)
        mrow[t] = mask[(long)q * Sc + tid + t * 256];

    float macc[8] = {0.f, 0.f, 0.f, 0.f, 0.f, 0.f, 0.f, 0.f};

    const float* pbase = g_scores + ((long)(b * Hc) * Sc + q) * Sc;
    float vn[8];
#pragma unroll
    for (int t = 0; t < 8; t++)
        vn[t] = pbase[tid + t * 256];

    for (int h = 0; h < Hc; h++) {
        __half* p16 = g_P16 + ((long)(b * Hc + h) * Sc + q) * Sc;
        float v[8];
        float mx = -INFINITY;
#pragma unroll
        for (int t = 0; t < 8; t++) {
            v[t] = vn[t] + mrow[t];
            mx = fmaxf(mx, v[t]);
        }
        if (h < Hc - 1) {                        // prefetch next head
            const float* pn = pbase + (long)(h + 1) * Sc * Sc;
#pragma unroll
            for (int t = 0; t < 8; t++)
                vn[t] = pn[tid + t * 256];
        }
#pragma unroll
        for (int o = 16; o > 0; o >>= 1)
            mx = fmaxf(mx, __shfl_xor_sync(0xffffffffu, mx, o));
        if (lane == 0) red[warp] = mx;
        __syncthreads();
        float bm = red[0];
#pragma unroll
        for (int w = 1; w < 8; w++) bm = fmaxf(bm, red[w]);
        __syncthreads();

        float s = 0.f;
#pragma unroll
        for (int t = 0; t < 8; t++) {
            v[t] = __expf(v[t] - bm);
            s += v[t];
        }
#pragma unroll
        for (int o = 16; o > 0; o >>= 1)
            s += __shfl_xor_sync(0xffffffffu, s, o);
        if (lane == 0) red[warp] = s;
        __syncthreads();
        float tot = 0.f;
#pragma unroll
        for (int w = 0; w < 8; w++) tot += red[w];
        __syncthreads();

        const float inv = 1.0f / tot;
#pragma unroll
        for (int t = 0; t < 8; t++) {
            float pe = v[t] * inv;
            p16[tid + t * 256] = __float2half(pe);
            macc[t] += pe;
        }
    }

#pragma unroll
    for (int t = 0; t < 8; t++)
        attn_out[(long)bq * Sc + tid + t * 256] = macc[t] * 0.125f;
}

// ---------------------------------------------------------------- launcher
extern "C" void kernel_launch(void* const* d_in, const int* in_sizes, int n_in,
                              void* d_out, int out_size)
{
    (void)in_sizes; (void)n_in; (void)out_size;

    const float* Zq   = (const float*)d_in[0];
    const float* Zkv  = (const float*)d_in[1];
    const float* mask = (const float*)d_in[2];
    const float* Wqkv = (const float*)d_in[3];
    const float* Wout = (const float*)d_in[4];

    float* out      = (float*)d_out;
    float* attn_out = out + QKV_N;

    float2 *gWT, *gWoT;
    float  *gQKV, *gCtx, *gS;
    __half *gVt16, *gP16;
    cudaGetSymbolAddress((void**)&gWT,   g_WT_hl);
    cudaGetSymbolAddress((void**)&gWoT,  g_WoT_hl);
    cudaGetSymbolAddress((void**)&gQKV,  g_QKV);
    cudaGetSymbolAddress((void**)&gVt16, g_Vt16);
    cudaGetSymbolAddress((void**)&gCtx,  g_ctx);
    cudaGetSymbolAddress((void**)&gS,    g_scores);
    cudaGetSymbolAddress((void**)&gP16,  g_P16);

    constexpr int SM_PROJ = 3 * (64 * 20 + 128 * 40) * 4;    // 76800
    constexpr int SM_SCR  = 3 * (128 * 20 + 128 * 20) * 4;   // 61440
    constexpr int SM_PV   = 3 * (256 * 40 + 64 * 40) * 2;    // 76800
    cudaFuncSetAttribute(mma_gemm<64, 128, 4, 2, true, 3, 3, true>,
                         cudaFuncAttributeMaxDynamicSharedMemorySize, SM_PROJ);
    cudaFuncSetAttribute(mma_gemm<64, 128, 4, 2, true, 2, 3, false>,
                         cudaFuncAttributeMaxDynamicSharedMemorySize, SM_PROJ);
    cudaFuncSetAttribute(mma_gemm<128, 128, 2, 4, false, 3, 3, false>,
                         cudaFuncAttributeMaxDynamicSharedMemorySize, SM_SCR);
    cudaFuncSetAttribute(pv_fp16_kernel,
                         cudaFuncAttributeMaxDynamicSharedMemorySize, SM_PV);

    dim3 blk(256);

    // 0) weight prep
    transpose_split_kernel<<<dim3(1536 / 32, 512 / 32, 1), blk>>>(
        Wqkv, 3 * Dc, gWT, Dc);
    transpose_split_kernel<<<dim3(512 / 32, 512 / 32, 1), blk>>>(
        Wout, Dc, gWoT, Dc);

    // 1) FUSED QKV projection: [8192,512] @ WT^T -> [8192,1536]
    //    Q cols [0,512) from Zq (x3); K cols [512,1024) from Zkv (x3);
    //    V cols [1024,1536) from Zkv (x2 via runtime guard).
    {
        dim3 g(3 * Dc / 128, (Bc * Sc) / 64, 1);   // 12 x 128 = 1536 CTAs
        mma_gemm<64, 128, 4, 2, true, 3, 3, true><<<g, blk, SM_PROJ>>>(
            Zq, Zkv, Dc, 0, 0,
            gWT, Dc, 0, 0,
            gQKV, 3 * Dc, 0, 0,
            Dc, 1.0f);
    }

    // 3b) V transpose -> fp16 per (b,h): [s,dk] -> [dk,s]; V at col 1024
    transpose_h16_kernel<<<dim3(DKc / 32, Sc / 32, Bc * Hc), blk>>>(
        gQKV + 2 * Dc, (long)Sc * 3 * Dc, DKc, 3 * Dc,
        gVt16, (long)DKc * Sc, Sc);

    // 4) scores = 0.125 * Q @ K^T per (b,h): Q at col 0, K at col 512
    {
        dim3 g(Sc / 128, Sc / 128, Bc * Hc);
        mma_gemm<128, 128, 2, 4, false, 3, 3, false><<<g, blk, SM_SCR>>>(
            gQKV, nullptr, 3 * Dc, (long)Sc * 3 * Dc, DKc,
            gQKV + Dc, 3 * Dc, (long)Sc * 3 * Dc, DKc,
            gS, Sc, (long)Hc * Sc * Sc, (long)Sc * Sc,
            DKc, 0.125f);
    }

    // 5) softmax (+mask) + head-mean; P written fp16 (prefetch variant)
    softmax_mean_kernel<<<Bc * Sc, blk>>>(mask, attn_out);

    // 6) ctx = P @ V per (b,h): fp16 x fp16, fp32 accum
    {
        dim3 g(1, Sc / 256, Bc * Hc);
        pv_fp16_kernel<<<g, blk, SM_PV>>>(gP16, gVt16, gCtx);
    }

    // 7) out = ctx @ Wout: raw ctx @ WoT hl, K=512, x2
    {
        dim3 g(Dc / 128, (Bc * Sc) / 64, 1);
        mma_gemm<64, 128, 4, 2, true, 2, 3, false><<<g, blk, SM_PROJ>>>(
            gCtx, nullptr, Dc, 0, 0,
            gWoT, Dc, 0, 0,
            out, Dc, 0, 0,
            Dc, 1.0f);
    }
}